// round 1
// baseline (speedup 1.0000x reference)
#include <cuda_runtime.h>
#include <math.h>

// Problem constants
#define BB 16
#define NN 1024
#define CC 1024
#define HH 16
#define DD 64
#define MTOT (BB * NN)      // 16384
#define QKVN (3 * CC)       // 3072

// Scratch (device globals: allocation-free rule)
__device__ float g_Q[BB * HH * NN * DD];   // [B,H,N,D]
__device__ float g_K[BB * HH * NN * DD];
__device__ float g_V[BB * HH * NN * DD];
__device__ float g_ctx[MTOT * CC];         // [B,N,C]

// ---------------------------------------------------------------------------
// SGEMM: C[M,N] = A[M,K] @ B[K,N] + bias
// BM=128, BN=128, BK=8, 256 threads, 8x8 microtile per thread.
// MODE 0: A = hidden_states, epilogue scatters into g_Q/g_K/g_V ([B,H,N,D]).
// MODE 1: A = g_ctx, epilogue writes Cout (d_out) with bias.
// ---------------------------------------------------------------------------
template <int MODE>
__global__ void __launch_bounds__(256, 2)
sgemm_kernel(const float* __restrict__ A, const float* __restrict__ Bm,
             const float* __restrict__ bias, float* __restrict__ Cout,
             int M, int N, int K)
{
    __shared__ float As[8][128];
    __shared__ float Bs[8][128];

    const int tid = threadIdx.x;
    const int bx = blockIdx.x, by = blockIdx.y;

    const float* Ap = (MODE == 1 ? g_ctx : A) + (size_t)by * 128 * K;
    const float* Bp = Bm + bx * 128;

    const int arow = tid >> 1;            // 0..127
    const int acol = (tid & 1) << 2;      // 0 or 4
    const int brow = tid >> 5;            // 0..7
    const int bcol = (tid & 31) << 2;     // 0..124
    const int tr = (tid >> 4) << 3;       // row microtile base 0..120
    const int tc = (tid & 15) << 3;       // col microtile base 0..120

    float acc[8][8];
#pragma unroll
    for (int i = 0; i < 8; i++)
#pragma unroll
        for (int j = 0; j < 8; j++) acc[i][j] = 0.0f;

    for (int k0 = 0; k0 < K; k0 += 8) {
        float4 a = *(const float4*)(Ap + (size_t)arow * K + k0 + acol);
        As[acol + 0][arow] = a.x;
        As[acol + 1][arow] = a.y;
        As[acol + 2][arow] = a.z;
        As[acol + 3][arow] = a.w;
        *(float4*)&Bs[brow][bcol] = *(const float4*)(Bp + (size_t)(k0 + brow) * N + bcol);
        __syncthreads();

#pragma unroll
        for (int k = 0; k < 8; k++) {
            float rm[8], rn[8];
#pragma unroll
            for (int i = 0; i < 8; i++) rm[i] = As[k][tr + i];
#pragma unroll
            for (int j = 0; j < 8; j++) rn[j] = Bs[k][tc + j];
#pragma unroll
            for (int i = 0; i < 8; i++)
#pragma unroll
                for (int j = 0; j < 8; j++)
                    acc[i][j] = fmaf(rm[i], rn[j], acc[i][j]);
        }
        __syncthreads();
    }

    const int row0 = by * 128 + tr;
    const int col0 = bx * 128 + tc;

    if (MODE == 0) {
#pragma unroll
        for (int i = 0; i < 8; i++) {
            const int row = row0 + i;
            const int bb = row >> 10;       // batch
            const int n  = row & 1023;      // token
#pragma unroll
            for (int j = 0; j < 8; j++) {
                const int col = col0 + j;
                const float v = acc[i][j] + bias[col];
                const int t = col >> 10;          // 0:Q 1:K 2:V
                const int rem = col & 1023;
                const int h = rem >> 6;
                const int d = rem & 63;
                const size_t idx = ((size_t)(bb * HH + h) * NN + n) * DD + d;
                if (t == 0)      g_Q[idx] = v;
                else if (t == 1) g_K[idx] = v;
                else             g_V[idx] = v;
            }
        }
    } else {
#pragma unroll
        for (int i = 0; i < 8; i++) {
            const int row = row0 + i;
#pragma unroll
            for (int j = 0; j < 8; j++) {
                const int col = col0 + j;
                Cout[(size_t)row * N + col] = acc[i][j] + bias[col];
            }
        }
    }
}

// ---------------------------------------------------------------------------
// Flash attention (fp32): one block = (b*H+h, 64-row M tile), 128 threads.
// BLOCK_M = BLOCK_N = 64, D = 64. Online softmax. Writes g_ctx [B,N,C].
// ---------------------------------------------------------------------------
#define SMP 65   // padded row stride (floats) to avoid bank conflicts

__global__ void __launch_bounds__(128)
attn_kernel()
{
    extern __shared__ float sm[];
    float* Qs = sm;                   // 64*65
    float* Ks = Qs + 64 * SMP;        // 64*65
    float* Vs = Ks + 64 * SMP;        // 64*65
    float* Ps = Vs + 64 * SMP;        // 64*65

    const int bh = blockIdx.x;        // 0..255
    const int mtile = blockIdx.y;     // 0..15
    const int tid = threadIdx.x;      // 0..127
    const int ty = tid >> 3;          // 0..15
    const int tx = tid & 7;           // 0..7
    const int r0 = ty << 2;           // 4 rows per thread
    const int c0 = tx << 3;           // 8 cols per thread

    const float* Qg = g_Q + ((size_t)bh * NN + mtile * 64) * DD;
    const float* Kg = g_K + (size_t)bh * NN * DD;
    const float* Vg = g_V + (size_t)bh * NN * DD;

    const float scale = 0.125f;       // 1/sqrt(64)

    // Load + prescale Q tile
    for (int idx = tid; idx < 64 * 16; idx += 128) {
        const int r = idx >> 4;
        const int c = (idx & 15) << 2;
        float4 v = *(const float4*)(Qg + r * 64 + c);
        Qs[r * SMP + c + 0] = v.x * scale;
        Qs[r * SMP + c + 1] = v.y * scale;
        Qs[r * SMP + c + 2] = v.z * scale;
        Qs[r * SMP + c + 3] = v.w * scale;
    }

    float m_i[4], l_i[4], o[4][8];
#pragma unroll
    for (int i = 0; i < 4; i++) {
        m_i[i] = -1e30f;
        l_i[i] = 0.0f;
#pragma unroll
        for (int d = 0; d < 8; d++) o[i][d] = 0.0f;
    }

    for (int nt = 0; nt < 16; nt++) {
        __syncthreads();  // previous-iter Ps/Vs reads complete before overwrite
        // Load K,V tiles
        for (int idx = tid; idx < 64 * 16; idx += 128) {
            const int r = idx >> 4;
            const int c = (idx & 15) << 2;
            float4 kv = *(const float4*)(Kg + (nt * 64 + r) * 64 + c);
            Ks[r * SMP + c + 0] = kv.x;
            Ks[r * SMP + c + 1] = kv.y;
            Ks[r * SMP + c + 2] = kv.z;
            Ks[r * SMP + c + 3] = kv.w;
            float4 vv = *(const float4*)(Vg + (nt * 64 + r) * 64 + c);
            Vs[r * SMP + c + 0] = vv.x;
            Vs[r * SMP + c + 1] = vv.y;
            Vs[r * SMP + c + 2] = vv.z;
            Vs[r * SMP + c + 3] = vv.w;
        }
        __syncthreads();

        // S = (Q*scale) @ K^T   (4x8 per thread)
        float s[4][8];
#pragma unroll
        for (int i = 0; i < 4; i++)
#pragma unroll
            for (int j = 0; j < 8; j++) s[i][j] = 0.0f;

#pragma unroll 8
        for (int k = 0; k < 64; k++) {
            float q[4], kk[8];
#pragma unroll
            for (int i = 0; i < 4; i++) q[i] = Qs[(r0 + i) * SMP + k];
#pragma unroll
            for (int j = 0; j < 8; j++) kk[j] = Ks[(c0 + j) * SMP + k];
#pragma unroll
            for (int i = 0; i < 4; i++)
#pragma unroll
                for (int j = 0; j < 8; j++)
                    s[i][j] = fmaf(q[i], kk[j], s[i][j]);
        }

        // Online softmax update (row groups = 8 lanes sharing ty)
#pragma unroll
        for (int i = 0; i < 4; i++) {
            float mx = s[i][0];
#pragma unroll
            for (int j = 1; j < 8; j++) mx = fmaxf(mx, s[i][j]);
            mx = fmaxf(mx, __shfl_xor_sync(0xffffffffu, mx, 1));
            mx = fmaxf(mx, __shfl_xor_sync(0xffffffffu, mx, 2));
            mx = fmaxf(mx, __shfl_xor_sync(0xffffffffu, mx, 4));
            const float mn = fmaxf(m_i[i], mx);
            const float alpha = __expf(m_i[i] - mn);
            float sum = 0.0f;
#pragma unroll
            for (int j = 0; j < 8; j++) {
                s[i][j] = __expf(s[i][j] - mn);
                sum += s[i][j];
            }
            sum += __shfl_xor_sync(0xffffffffu, sum, 1);
            sum += __shfl_xor_sync(0xffffffffu, sum, 2);
            sum += __shfl_xor_sync(0xffffffffu, sum, 4);
            l_i[i] = l_i[i] * alpha + sum;
            m_i[i] = mn;
#pragma unroll
            for (int d = 0; d < 8; d++) o[i][d] *= alpha;
        }

        // Stage P through smem for the PV GEMM
#pragma unroll
        for (int i = 0; i < 4; i++)
#pragma unroll
            for (int j = 0; j < 8; j++)
                Ps[(r0 + i) * SMP + c0 + j] = s[i][j];
        __syncthreads();

        // O += P @ V
#pragma unroll 8
        for (int j = 0; j < 64; j++) {
            float p[4], v[8];
#pragma unroll
            for (int i = 0; i < 4; i++) p[i] = Ps[(r0 + i) * SMP + j];
#pragma unroll
            for (int d = 0; d < 8; d++) v[d] = Vs[j * SMP + c0 + d];
#pragma unroll
            for (int i = 0; i < 4; i++)
#pragma unroll
                for (int d = 0; d < 8; d++)
                    o[i][d] = fmaf(p[i], v[d], o[i][d]);
        }
    }

    // Epilogue: ctx[b, n, h*64 + d] = o / l
    const int b = bh >> 4;
    const int h = bh & 15;
    float* dst = g_ctx + ((size_t)(b * NN) + mtile * 64) * CC + h * DD;
#pragma unroll
    for (int i = 0; i < 4; i++) {
        const float inv = 1.0f / l_i[i];
#pragma unroll
        for (int d = 0; d < 8; d++)
            dst[(size_t)(r0 + i) * CC + c0 + d] = o[i][d] * inv;
    }
}

// ---------------------------------------------------------------------------
extern "C" void kernel_launch(void* const* d_in, const int* in_sizes, int n_in,
                              void* d_out, int out_size)
{
    const float* hidden = (const float*)d_in[0];
    const float* qkv_w  = (const float*)d_in[1];
    const float* qkv_b  = (const float*)d_in[2];
    const float* proj_w = (const float*)d_in[3];
    const float* proj_b = (const float*)d_in[4];
    float* out = (float*)d_out;

    // 1) QKV GEMM + scatter: [16384,1024] @ [1024,3072]
    {
        dim3 grid(QKVN / 128, MTOT / 128);  // (24, 128)
        sgemm_kernel<0><<<grid, 256>>>(hidden, qkv_w, qkv_b, nullptr,
                                       MTOT, QKVN, CC);
    }

    // 2) Flash attention
    {
        const int smem_bytes = 4 * 64 * SMP * sizeof(float);  // 66,560 B
        cudaFuncSetAttribute(attn_kernel,
                             cudaFuncAttributeMaxDynamicSharedMemorySize,
                             smem_bytes);
        dim3 grid(BB * HH, NN / 64);  // (256, 16)
        attn_kernel<<<grid, 128, smem_bytes>>>();
    }

    // 3) Output projection: [16384,1024] @ [1024,1024] + bias
    {
        dim3 grid(CC / 128, MTOT / 128);  // (8, 128)
        sgemm_kernel<1><<<grid, 256>>>(nullptr, proj_w, proj_b, out,
                                       MTOT, CC, CC);
    }
}

// round 3
// speedup vs baseline: 1.6639x; 1.6639x over previous
#include <cuda_runtime.h>
#include <cuda_bf16.h>
#include <cstdint>
#include <math.h>

// ---------------------------------------------------------------------------
// Problem constants
// ---------------------------------------------------------------------------
#define BB 16
#define NN 1024
#define CC 1024
#define HH 16
#define DD 64
#define MTOT (BB * NN)      // 16384
#define KP 3072             // expanded K' = 3*1024 (bf16x3 split)
#define NCHUNK 48           // KP / 64

// ---------------------------------------------------------------------------
// Scratch (device globals: allocation-free rule)
// ---------------------------------------------------------------------------
__device__ float g_Q[MTOT * CC];           // [B,H,N,D]
__device__ float g_K[MTOT * CC];
__device__ float g_V[MTOT * CC];
__device__ float g_ctx[MTOT * CC];         // [B,N,C]
__device__ __nv_bfloat16 g_A3[(size_t)MTOT * KP];   // hidden split  [M, 3K] = [ah|ah|al]
__device__ __nv_bfloat16 g_C3[(size_t)MTOT * KP];   // ctx split
__device__ __nv_bfloat16 g_W3[(size_t)3072 * KP];   // qkv_w^T split [N, 3K] = [bh|bl|bh]
__device__ __nv_bfloat16 g_P3[(size_t)1024 * KP];   // proj_w^T split

// ---------------------------------------------------------------------------
// PTX helpers (base ISA only: cp.async / ldmatrix / mma.sync — no tcgen05)
// ---------------------------------------------------------------------------
__device__ __forceinline__ uint32_t smem_u32(const void* p) {
    uint32_t a;
    asm("{ .reg .u64 t; cvta.to.shared.u64 t, %1; cvt.u32.u64 %0, t; }"
        : "=r"(a) : "l"(p));
    return a;
}

__device__ __forceinline__ void cpa16(uint32_t sdst, const void* gsrc) {
    asm volatile("cp.async.cg.shared.global [%0], [%1], 16;" :: "r"(sdst), "l"(gsrc));
}
#define CPA_COMMIT() asm volatile("cp.async.commit_group;" ::: "memory")
#define CPA_WAIT(n)  asm volatile("cp.async.wait_group %0;" :: "n"(n) : "memory")

__device__ __forceinline__ void ldsm_x4(uint32_t* r, uint32_t addr) {
    asm volatile("ldmatrix.sync.aligned.m8n8.x4.shared.b16 {%0,%1,%2,%3}, [%4];"
                 : "=r"(r[0]), "=r"(r[1]), "=r"(r[2]), "=r"(r[3]) : "r"(addr));
}

__device__ __forceinline__ void mma16816(float* c, const uint32_t* a, const uint32_t* b) {
    asm volatile(
        "mma.sync.aligned.m16n8k16.row.col.f32.bf16.bf16.f32 "
        "{%0,%1,%2,%3}, {%4,%5,%6,%7}, {%8,%9}, {%0,%1,%2,%3};"
        : "+f"(c[0]), "+f"(c[1]), "+f"(c[2]), "+f"(c[3])
        : "r"(a[0]), "r"(a[1]), "r"(a[2]), "r"(a[3]), "r"(b[0]), "r"(b[1]));
}

// ---------------------------------------------------------------------------
// HMMA bf16 GEMM: 128x128 tile, BK=64, 2-stage cp.async pipeline, 256 threads.
// A [M, KP], B [N, KP] both K-major bf16 (bf16x3 expanded).
// MODE 0: scatter epilogue -> g_Q/g_K/g_V with bias. MODE 1: Cout [M,1024]+bias.
// ---------------------------------------------------------------------------
#define STAGE_BYTES 32768            // A 16KB + B 16KB
#define GEMM_SMEM   (2 * STAGE_BYTES)

__device__ __forceinline__ void load_tiles(uint32_t sb, int stage,
                                           const __nv_bfloat16* Ap,
                                           const __nv_bfloat16* Bp,
                                           int chunk, int tid) {
    const int kb = chunk * 64;
    const uint32_t abase = sb + stage * STAGE_BYTES;
    const uint32_t bbase = abase + 16384;
#pragma unroll
    for (int i = 0; i < 4; i++) {           // A: 128 rows x 64 bf16 = 1024 x 16B
        int u = tid + i * 256;
        int row = u >> 3, cu = u & 7;
        uint32_t bo = row * 128 + cu * 16;
        uint32_t sw = bo ^ ((bo >> 3) & 0x70);
        cpa16(abase + sw, Ap + (size_t)row * KP + kb + cu * 8);
    }
#pragma unroll
    for (int i = 0; i < 4; i++) {           // B: 128 rows x 64 bf16
        int u = tid + i * 256;
        int row = u >> 3, cu = u & 7;
        uint32_t bo = row * 128 + cu * 16;
        uint32_t sw = bo ^ ((bo >> 3) & 0x70);
        cpa16(bbase + sw, Bp + (size_t)row * KP + kb + cu * 8);
    }
}

template <int MODE>
__global__ void __launch_bounds__(256, 2)
hmma_gemm(const float* __restrict__ bias, float* __restrict__ Cout)
{
    extern __shared__ __align__(1024) char smem[];
    const uint32_t sb = smem_u32(smem);
    const int tid = threadIdx.x, wid = tid >> 5, lane = tid & 31;
    const int bx = blockIdx.x, by = blockIdx.y;

    const __nv_bfloat16* A3 = (MODE == 0) ? g_A3 : g_C3;
    const __nv_bfloat16* B3 = (MODE == 0) ? g_W3 : g_P3;
    const __nv_bfloat16* Ap = A3 + (size_t)by * 128 * KP;
    const __nv_bfloat16* Bp = B3 + (size_t)bx * 128 * KP;

    const int wm = (wid >> 2) * 64;         // warp m offset (0 or 64)
    const int wn = (wid & 3) * 32;          // warp n offset (0/32/64/96)

    float acc[4][4][4];
#pragma unroll
    for (int i = 0; i < 4; i++)
#pragma unroll
        for (int j = 0; j < 4; j++)
#pragma unroll
            for (int v = 0; v < 4; v++) acc[i][j][v] = 0.0f;

    // ldmatrix lane addressing (within tile, before swizzle)
    const int a_r = lane & 15;              // + wm + mt*16
    const int a_c = (lane >> 4) << 3;       // + k0
    const int b_r = (lane & 7) + ((lane >> 4) << 3);  // + wn + nt2*16
    const int b_c = ((lane >> 3) & 1) << 3;           // + k0

    // prologue: stage 0 <- chunk 0
    load_tiles(sb, 0, Ap, Bp, 0, tid);
    CPA_COMMIT();

    for (int c = 0; c < NCHUNK; c++) {
        const int s = c & 1;
        CPA_WAIT(0);                        // chunk c resident
        __syncthreads();                    // stage s^1 fully consumed (prev iter)

        if (c + 1 < NCHUNK)
            load_tiles(sb, s ^ 1, Ap, Bp, c + 1, tid);
        CPA_COMMIT();                       // uniform commit (may be empty)

        const uint32_t abase = sb + s * STAGE_BYTES;
        const uint32_t bbase = abase + 16384;

#pragma unroll
        for (int ks = 0; ks < 4; ks++) {
            const int k0 = ks * 16;
            uint32_t af[4][4], bf[2][4];
#pragma unroll
            for (int mt = 0; mt < 4; mt++) {
                uint32_t bo = (wm + mt * 16 + a_r) * 128 + (k0 + a_c) * 2;
                ldsm_x4(af[mt], abase + (bo ^ ((bo >> 3) & 0x70)));
            }
#pragma unroll
            for (int nt2 = 0; nt2 < 2; nt2++) {
                uint32_t bo = (wn + nt2 * 16 + b_r) * 128 + (k0 + b_c) * 2;
                ldsm_x4(bf[nt2], bbase + (bo ^ ((bo >> 3) & 0x70)));
            }
#pragma unroll
            for (int mt = 0; mt < 4; mt++)
#pragma unroll
                for (int nt = 0; nt < 4; nt++)
                    mma16816(acc[mt][nt], af[mt], &bf[nt >> 1][(nt & 1) * 2]);
        }
        __syncthreads();                    // stage s free before next-next load
    }

    // ------------------- epilogue: direct float2 stores --------------------
    const int tr = lane >> 2;
    const int tc = (lane & 3) << 1;
#pragma unroll
    for (int mt = 0; mt < 4; mt++) {
#pragma unroll
        for (int nt = 0; nt < 4; nt++) {
            const int n = bx * 128 + wn + nt * 8 + tc;
            const float b0 = bias[n], b1 = bias[n + 1];
#pragma unroll
            for (int half = 0; half < 2; half++) {
                const int m = by * 128 + wm + mt * 16 + tr + half * 8;
                const float v0 = acc[mt][nt][half * 2 + 0] + b0;
                const float v1 = acc[mt][nt][half * 2 + 1] + b1;
                if (MODE == 1) {
                    float2 w = make_float2(v0, v1);
                    *(float2*)&Cout[(size_t)m * CC + n] = w;
                } else {
                    const int bb = m >> 10, tok = m & 1023;
                    const int t = n >> 10;
                    const int rem = n & 1023;
                    const int h = rem >> 6, d = rem & 63;
                    const size_t idx = ((size_t)(bb * HH + h) * NN + tok) * DD + d;
                    float2 w = make_float2(v0, v1);
                    if (t == 0)      *(float2*)&g_Q[idx] = w;
                    else if (t == 1) *(float2*)&g_K[idx] = w;
                    else             *(float2*)&g_V[idx] = w;
                }
            }
        }
    }
}

// ---------------------------------------------------------------------------
// Preprocessing: bf16 hi/lo splits
// ---------------------------------------------------------------------------
template <int DST>
__global__ void split_act(const float* __restrict__ src)
{
    __nv_bfloat16* dst = (DST == 0) ? g_A3 : g_C3;
    const float* s = (DST == 0) ? src : g_ctx;
    const int i = blockIdx.x * 256 + threadIdx.x;   // unit of 4 floats
    const int m = i >> 8;
    const int k = (i & 255) << 2;
    float4 v = ((const float4*)s)[i];

    __nv_bfloat16 h0 = __float2bfloat16(v.x), h1 = __float2bfloat16(v.y);
    __nv_bfloat16 h2 = __float2bfloat16(v.z), h3 = __float2bfloat16(v.w);
    __nv_bfloat16 l0 = __float2bfloat16(v.x - __bfloat162float(h0));
    __nv_bfloat16 l1 = __float2bfloat16(v.y - __bfloat162float(h1));
    __nv_bfloat16 l2 = __float2bfloat16(v.z - __bfloat162float(h2));
    __nv_bfloat16 l3 = __float2bfloat16(v.w - __bfloat162float(h3));

    __nv_bfloat162 hA, hB, lA, lB;
    hA.x = h0; hA.y = h1; hB.x = h2; hB.y = h3;
    lA.x = l0; lA.y = l1; lB.x = l2; lB.y = l3;

    __nv_bfloat16* row = dst + (size_t)m * KP;
    *(__nv_bfloat162*)(row + k)          = hA;
    *(__nv_bfloat162*)(row + k + 2)      = hB;
    *(__nv_bfloat162*)(row + 1024 + k)   = hA;
    *(__nv_bfloat162*)(row + 1026 + k)   = hB;
    *(__nv_bfloat162*)(row + 2048 + k)   = lA;
    *(__nv_bfloat162*)(row + 2050 + k)   = lB;
}

template <int W>
__global__ void split_w(const float* __restrict__ w)
{
    __nv_bfloat16* dst = (W == 0) ? g_W3 : g_P3;
    const int Nw = (W == 0) ? 3072 : 1024;
    __shared__ float t[32][33];
    const int n0 = blockIdx.x * 32, k0 = blockIdx.y * 32;
    const int tx = threadIdx.x, ty = threadIdx.y;   // block (32, 8)

#pragma unroll
    for (int i = 0; i < 32; i += 8)
        t[ty + i][tx] = w[(size_t)(k0 + ty + i) * Nw + n0 + tx];
    __syncthreads();
#pragma unroll
    for (int i = 0; i < 32; i += 8) {
        const int n = n0 + ty + i, k = k0 + tx;
        const float x = t[tx][ty + i];
        const __nv_bfloat16 h = __float2bfloat16(x);
        const __nv_bfloat16 l = __float2bfloat16(x - __bfloat162float(h));
        __nv_bfloat16* row = dst + (size_t)n * KP;
        row[k] = h;
        row[1024 + k] = l;
        row[2048 + k] = h;
    }
}

// ---------------------------------------------------------------------------
// Flash attention (fp32, validated in R1): grid (256, 16), 128 threads
// ---------------------------------------------------------------------------
#define SMP 65

__global__ void __launch_bounds__(128)
attn_kernel()
{
    extern __shared__ float sm[];
    float* Qs = sm;
    float* Ks = Qs + 64 * SMP;
    float* Vs = Ks + 64 * SMP;
    float* Ps = Vs + 64 * SMP;

    const int bh = blockIdx.x;
    const int mtile = blockIdx.y;
    const int tid = threadIdx.x;
    const int ty = tid >> 3;
    const int tx = tid & 7;
    const int r0 = ty << 2;
    const int c0 = tx << 3;

    const float* Qg = g_Q + ((size_t)bh * NN + mtile * 64) * DD;
    const float* Kg = g_K + (size_t)bh * NN * DD;
    const float* Vg = g_V + (size_t)bh * NN * DD;

    const float scale = 0.125f;

    for (int idx = tid; idx < 64 * 16; idx += 128) {
        const int r = idx >> 4;
        const int c = (idx & 15) << 2;
        float4 v = *(const float4*)(Qg + r * 64 + c);
        Qs[r * SMP + c + 0] = v.x * scale;
        Qs[r * SMP + c + 1] = v.y * scale;
        Qs[r * SMP + c + 2] = v.z * scale;
        Qs[r * SMP + c + 3] = v.w * scale;
    }

    float m_i[4], l_i[4], o[4][8];
#pragma unroll
    for (int i = 0; i < 4; i++) {
        m_i[i] = -1e30f;
        l_i[i] = 0.0f;
#pragma unroll
        for (int d = 0; d < 8; d++) o[i][d] = 0.0f;
    }

    for (int nt = 0; nt < 16; nt++) {
        __syncthreads();
        for (int idx = tid; idx < 64 * 16; idx += 128) {
            const int r = idx >> 4;
            const int c = (idx & 15) << 2;
            float4 kv = *(const float4*)(Kg + (nt * 64 + r) * 64 + c);
            Ks[r * SMP + c + 0] = kv.x;
            Ks[r * SMP + c + 1] = kv.y;
            Ks[r * SMP + c + 2] = kv.z;
            Ks[r * SMP + c + 3] = kv.w;
            float4 vv = *(const float4*)(Vg + (nt * 64 + r) * 64 + c);
            Vs[r * SMP + c + 0] = vv.x;
            Vs[r * SMP + c + 1] = vv.y;
            Vs[r * SMP + c + 2] = vv.z;
            Vs[r * SMP + c + 3] = vv.w;
        }
        __syncthreads();

        float s[4][8];
#pragma unroll
        for (int i = 0; i < 4; i++)
#pragma unroll
            for (int j = 0; j < 8; j++) s[i][j] = 0.0f;

#pragma unroll 8
        for (int k = 0; k < 64; k++) {
            float q[4], kk[8];
#pragma unroll
            for (int i = 0; i < 4; i++) q[i] = Qs[(r0 + i) * SMP + k];
#pragma unroll
            for (int j = 0; j < 8; j++) kk[j] = Ks[(c0 + j) * SMP + k];
#pragma unroll
            for (int i = 0; i < 4; i++)
#pragma unroll
                for (int j = 0; j < 8; j++)
                    s[i][j] = fmaf(q[i], kk[j], s[i][j]);
        }

#pragma unroll
        for (int i = 0; i < 4; i++) {
            float mx = s[i][0];
#pragma unroll
            for (int j = 1; j < 8; j++) mx = fmaxf(mx, s[i][j]);
            mx = fmaxf(mx, __shfl_xor_sync(0xffffffffu, mx, 1));
            mx = fmaxf(mx, __shfl_xor_sync(0xffffffffu, mx, 2));
            mx = fmaxf(mx, __shfl_xor_sync(0xffffffffu, mx, 4));
            const float mn = fmaxf(m_i[i], mx);
            const float alpha = __expf(m_i[i] - mn);
            float sum = 0.0f;
#pragma unroll
            for (int j = 0; j < 8; j++) {
                s[i][j] = __expf(s[i][j] - mn);
                sum += s[i][j];
            }
            sum += __shfl_xor_sync(0xffffffffu, sum, 1);
            sum += __shfl_xor_sync(0xffffffffu, sum, 2);
            sum += __shfl_xor_sync(0xffffffffu, sum, 4);
            l_i[i] = l_i[i] * alpha + sum;
            m_i[i] = mn;
#pragma unroll
            for (int d = 0; d < 8; d++) o[i][d] *= alpha;
        }

#pragma unroll
        for (int i = 0; i < 4; i++)
#pragma unroll
            for (int j = 0; j < 8; j++)
                Ps[(r0 + i) * SMP + c0 + j] = s[i][j];
        __syncthreads();

#pragma unroll 8
        for (int j = 0; j < 64; j++) {
            float p[4], v[8];
#pragma unroll
            for (int i = 0; i < 4; i++) p[i] = Ps[(r0 + i) * SMP + j];
#pragma unroll
            for (int d = 0; d < 8; d++) v[d] = Vs[j * SMP + c0 + d];
#pragma unroll
            for (int i = 0; i < 4; i++)
#pragma unroll
                for (int d = 0; d < 8; d++)
                    o[i][d] = fmaf(p[i], v[d], o[i][d]);
        }
    }

    const int b = bh >> 4;
    const int h = bh & 15;
    float* dst = g_ctx + ((size_t)(b * NN) + mtile * 64) * CC + h * DD;
#pragma unroll
    for (int i = 0; i < 4; i++) {
        const float inv = 1.0f / l_i[i];
#pragma unroll
        for (int d = 0; d < 8; d++)
            dst[(size_t)(r0 + i) * CC + c0 + d] = o[i][d] * inv;
    }
}

// ---------------------------------------------------------------------------
extern "C" void kernel_launch(void* const* d_in, const int* in_sizes, int n_in,
                              void* d_out, int out_size)
{
    const float* hidden = (const float*)d_in[0];
    const float* qkv_w  = (const float*)d_in[1];
    const float* qkv_b  = (const float*)d_in[2];
    const float* proj_w = (const float*)d_in[3];
    const float* proj_b = (const float*)d_in[4];
    float* out = (float*)d_out;

    cudaFuncSetAttribute(hmma_gemm<0>, cudaFuncAttributeMaxDynamicSharedMemorySize, GEMM_SMEM);
    cudaFuncSetAttribute(hmma_gemm<1>, cudaFuncAttributeMaxDynamicSharedMemorySize, GEMM_SMEM);
    cudaFuncSetAttribute(attn_kernel, cudaFuncAttributeMaxDynamicSharedMemorySize,
                         4 * 64 * SMP * (int)sizeof(float));

    // 1) splits
    split_act<0><<<16384, 256>>>(hidden);
    {
        dim3 g0(3072 / 32, 1024 / 32);
        split_w<0><<<g0, dim3(32, 8)>>>(qkv_w);
        dim3 g1(1024 / 32, 1024 / 32);
        split_w<1><<<g1, dim3(32, 8)>>>(proj_w);
    }

    // 2) QKV GEMM (HMMA bf16x3) -> Q/K/V scatter
    {
        dim3 grid(3072 / 128, MTOT / 128);   // (24, 128)
        hmma_gemm<0><<<grid, 256, GEMM_SMEM>>>(qkv_b, nullptr);
    }

    // 3) Flash attention (fp32)
    {
        const int smem_bytes = 4 * 64 * SMP * sizeof(float);
        dim3 grid(BB * HH, NN / 64);
        attn_kernel<<<grid, 128, smem_bytes>>>();
    }

    // 4) split ctx
    split_act<1><<<16384, 256>>>(nullptr);

    // 5) projection GEMM -> out
    {
        dim3 grid(1024 / 128, MTOT / 128);   // (8, 128)
        hmma_gemm<1><<<grid, 256, GEMM_SMEM>>>(proj_b, out);
    }
}

// round 5
// speedup vs baseline: 3.6988x; 2.2230x over previous
#include <cuda_runtime.h>
#include <cuda_bf16.h>
#include <cstdint>
#include <string.h>
#include <math.h>

// ---------------------------------------------------------------------------
// Problem constants
// ---------------------------------------------------------------------------
#define BB 16
#define NN 1024
#define CC 1024
#define HH 16
#define DD 64
#define MTOT (BB * NN)      // 16384
#define KP 3072             // expanded K' = 3*1024 (bf16x3 split)
#define NCHUNK 48           // KP / 64
#define QSCALE 0.1803368801111204f   // 0.125 * log2(e)

// ---------------------------------------------------------------------------
// Scratch (device globals: allocation-free rule)
// ---------------------------------------------------------------------------
__device__ __nv_bfloat16 g_Qh[(size_t)MTOT * CC];   // [bh][tok][64], prescaled
__device__ __nv_bfloat16 g_Ql[(size_t)MTOT * CC];
__device__ __nv_bfloat16 g_Kh[(size_t)MTOT * CC];
__device__ __nv_bfloat16 g_Kl[(size_t)MTOT * CC];
__device__ __nv_bfloat16 g_Vh[(size_t)MTOT * CC];
__device__ __nv_bfloat16 g_Vl[(size_t)MTOT * CC];
__device__ __nv_bfloat16 g_A3[(size_t)MTOT * KP];   // hidden split  [ah|ah|al]
__device__ __nv_bfloat16 g_C3[(size_t)MTOT * KP];   // ctx split (written by attn)
__device__ __nv_bfloat16 g_W3[(size_t)3072 * KP];   // qkv_w^T split [bh|bl|bh]
__device__ __nv_bfloat16 g_P3[(size_t)1024 * KP];   // proj_w^T split

// ---------------------------------------------------------------------------
// PTX helpers (base ISA only)
// ---------------------------------------------------------------------------
__device__ __forceinline__ uint32_t smem_u32(const void* p) {
    uint32_t a;
    asm("{ .reg .u64 t; cvta.to.shared.u64 t, %1; cvt.u32.u64 %0, t; }"
        : "=r"(a) : "l"(p));
    return a;
}
__device__ __forceinline__ void cpa16(uint32_t sdst, const void* gsrc) {
    asm volatile("cp.async.cg.shared.global [%0], [%1], 16;" :: "r"(sdst), "l"(gsrc));
}
#define CPA_COMMIT() asm volatile("cp.async.commit_group;" ::: "memory")
#define CPA_WAIT(n)  asm volatile("cp.async.wait_group %0;" :: "n"(n) : "memory")

__device__ __forceinline__ void ldsm_x4(uint32_t* r, uint32_t addr) {
    asm volatile("ldmatrix.sync.aligned.m8n8.x4.shared.b16 {%0,%1,%2,%3}, [%4];"
                 : "=r"(r[0]), "=r"(r[1]), "=r"(r[2]), "=r"(r[3]) : "r"(addr));
}
__device__ __forceinline__ void ldsm_x4_t(uint32_t* r, uint32_t addr) {
    asm volatile("ldmatrix.sync.aligned.m8n8.x4.trans.shared.b16 {%0,%1,%2,%3}, [%4];"
                 : "=r"(r[0]), "=r"(r[1]), "=r"(r[2]), "=r"(r[3]) : "r"(addr));
}
__device__ __forceinline__ void mma16816(float* c, const uint32_t* a, const uint32_t* b) {
    asm volatile(
        "mma.sync.aligned.m16n8k16.row.col.f32.bf16.bf16.f32 "
        "{%0,%1,%2,%3}, {%4,%5,%6,%7}, {%8,%9}, {%0,%1,%2,%3};"
        : "+f"(c[0]), "+f"(c[1]), "+f"(c[2]), "+f"(c[3])
        : "r"(a[0]), "r"(a[1]), "r"(a[2]), "r"(a[3]), "r"(b[0]), "r"(b[1]));
}
__device__ __forceinline__ float ex2(float x) {
    float y;
    asm("ex2.approx.ftz.f32 %0, %1;" : "=f"(y) : "f"(x));
    return y;
}
__device__ __forceinline__ uint32_t packbf(float a, float b) {
    __nv_bfloat162 t;
    t.x = __float2bfloat16(a);
    t.y = __float2bfloat16(b);
    uint32_t u;
    memcpy(&u, &t, 4);
    return u;
}
// pack hi, return residuals
__device__ __forceinline__ uint32_t packbf_res(float a, float b, float& ra, float& rb) {
    __nv_bfloat162 t;
    t.x = __float2bfloat16(a);
    t.y = __float2bfloat16(b);
    ra = a - __bfloat162float(t.x);
    rb = b - __bfloat162float(t.y);
    uint32_t u;
    memcpy(&u, &t, 4);
    return u;
}
__device__ __forceinline__ uint32_t sw128(uint32_t bo) { return bo ^ ((bo >> 3) & 0x70); }

// ---------------------------------------------------------------------------
// HMMA bf16 GEMM: 128x128 tile, BK=64, 2-stage cp.async pipeline, 256 threads.
// MODE 0: -> Q/K/V bf16 hi/lo scatter (Q prescaled). MODE 1: Cout fp32 + bias.
// ---------------------------------------------------------------------------
#define STAGE_BYTES 32768
#define GEMM_SMEM   (2 * STAGE_BYTES)

__device__ __forceinline__ void load_tiles(uint32_t sb, int stage,
                                           const __nv_bfloat16* Ap,
                                           const __nv_bfloat16* Bp,
                                           int chunk, int tid) {
    const int kb = chunk * 64;
    const uint32_t abase = sb + stage * STAGE_BYTES;
    const uint32_t bbase = abase + 16384;
#pragma unroll
    for (int i = 0; i < 4; i++) {
        int u = tid + i * 256;
        int row = u >> 3, cu = u & 7;
        cpa16(abase + sw128(row * 128 + cu * 16), Ap + (size_t)row * KP + kb + cu * 8);
    }
#pragma unroll
    for (int i = 0; i < 4; i++) {
        int u = tid + i * 256;
        int row = u >> 3, cu = u & 7;
        cpa16(bbase + sw128(row * 128 + cu * 16), Bp + (size_t)row * KP + kb + cu * 8);
    }
}

template <int MODE>
__global__ void __launch_bounds__(256, 2)
hmma_gemm(const float* __restrict__ bias, float* __restrict__ Cout)
{
    extern __shared__ __align__(1024) char smem[];
    const uint32_t sb = smem_u32(smem);
    const int tid = threadIdx.x, wid = tid >> 5, lane = tid & 31;
    const int bx = blockIdx.x, by = blockIdx.y;

    const __nv_bfloat16* A3 = (MODE == 0) ? g_A3 : g_C3;
    const __nv_bfloat16* B3 = (MODE == 0) ? g_W3 : g_P3;
    const __nv_bfloat16* Ap = A3 + (size_t)by * 128 * KP;
    const __nv_bfloat16* Bp = B3 + (size_t)bx * 128 * KP;

    const int wm = (wid >> 2) * 64;
    const int wn = (wid & 3) * 32;

    float acc[4][4][4];
#pragma unroll
    for (int i = 0; i < 4; i++)
#pragma unroll
        for (int j = 0; j < 4; j++)
#pragma unroll
            for (int v = 0; v < 4; v++) acc[i][j][v] = 0.0f;

    const int a_r = lane & 15;
    const int a_c = (lane >> 4) << 3;
    const int b_r = (lane & 7) + ((lane >> 4) << 3);
    const int b_c = ((lane >> 3) & 1) << 3;

    load_tiles(sb, 0, Ap, Bp, 0, tid);
    CPA_COMMIT();

    for (int c = 0; c < NCHUNK; c++) {
        const int s = c & 1;
        CPA_WAIT(0);
        __syncthreads();

        if (c + 1 < NCHUNK)
            load_tiles(sb, s ^ 1, Ap, Bp, c + 1, tid);
        CPA_COMMIT();

        const uint32_t abase = sb + s * STAGE_BYTES;
        const uint32_t bbase = abase + 16384;

#pragma unroll
        for (int ks = 0; ks < 4; ks++) {
            const int k0 = ks * 16;
            uint32_t af[4][4], bf[2][4];
#pragma unroll
            for (int mt = 0; mt < 4; mt++)
                ldsm_x4(af[mt], abase + sw128((wm + mt * 16 + a_r) * 128 + (k0 + a_c) * 2));
#pragma unroll
            for (int nt2 = 0; nt2 < 2; nt2++)
                ldsm_x4(bf[nt2], bbase + sw128((wn + nt2 * 16 + b_r) * 128 + (k0 + b_c) * 2));
#pragma unroll
            for (int mt = 0; mt < 4; mt++)
#pragma unroll
                for (int nt = 0; nt < 4; nt++)
                    mma16816(acc[mt][nt], af[mt], &bf[nt >> 1][(nt & 1) * 2]);
        }
        __syncthreads();
    }

    // ------------------- epilogue --------------------
    const int tr = lane >> 2;
    const int tc = (lane & 3) << 1;
#pragma unroll
    for (int mt = 0; mt < 4; mt++) {
#pragma unroll
        for (int nt = 0; nt < 4; nt++) {
            const int n = bx * 128 + wn + nt * 8 + tc;
            const float b0 = bias[n], b1 = bias[n + 1];
#pragma unroll
            for (int half = 0; half < 2; half++) {
                const int m = by * 128 + wm + mt * 16 + tr + half * 8;
                float v0 = acc[mt][nt][half * 2 + 0] + b0;
                float v1 = acc[mt][nt][half * 2 + 1] + b1;
                if (MODE == 1) {
                    *(float2*)&Cout[(size_t)m * CC + n] = make_float2(v0, v1);
                } else {
                    const int bb = m >> 10, tok = m & 1023;
                    const int t = n >> 10;
                    const int rem = n & 1023;
                    const int h = rem >> 6, d = rem & 63;
                    const size_t idx = ((size_t)(bb * HH + h) * NN + tok) * DD + d;
                    if (t == 0) { v0 *= QSCALE; v1 *= QSCALE; }
                    float r0, r1;
                    uint32_t hi = packbf_res(v0, v1, r0, r1);
                    uint32_t lo = packbf(r0, r1);
                    __nv_bfloat16 *ph, *pl;
                    if (t == 0)      { ph = g_Qh; pl = g_Ql; }
                    else if (t == 1) { ph = g_Kh; pl = g_Kl; }
                    else             { ph = g_Vh; pl = g_Vl; }
                    *(uint32_t*)(ph + idx) = hi;
                    *(uint32_t*)(pl + idx) = lo;
                }
            }
        }
    }
}

// ---------------------------------------------------------------------------
// Flash attention, HMMA bf16 3-pass. Block = (bh, 128 Q rows), 256 threads.
// KV tiles of 64 rows, double-buffered cp.async. Writes g_C3 (bf16x3).
// ---------------------------------------------------------------------------
#define AT_OQH 0
#define AT_OQL 16384
#define AT_ST(s) (32768 + (s) * 32768)
#define AT_KH 0
#define AT_KL 8192
#define AT_VH 16384
#define AT_VL 24576
#define ATTN_SMEM 98304

__device__ __forceinline__ void attn_load_kv(uint32_t sb, int stage, size_t goff,
                                             int j0, int tid) {
    const uint32_t base = sb + AT_ST(stage);
    const __nv_bfloat16* gp[4] = {g_Kh + goff, g_Kl + goff, g_Vh + goff, g_Vl + goff};
#pragma unroll
    for (int a = 0; a < 4; a++) {
#pragma unroll
        for (int i = 0; i < 2; i++) {
            int u = tid + i * 256;           // 512 units of 16B per array
            int row = u >> 3, cu = u & 7;
            cpa16(base + a * 8192 + sw128(row * 128 + cu * 16),
                  gp[a] + (size_t)(j0 + row) * 64 + cu * 8);
        }
    }
}

__global__ void __launch_bounds__(256, 1)
attn_hmma()
{
    extern __shared__ __align__(1024) char smem[];
    const uint32_t sb = smem_u32(smem);
    const int tid = threadIdx.x, wid = tid >> 5, lane = tid & 31;
    const int bh = blockIdx.x;       // 0..255
    const int mt = blockIdx.y;       // 0..7 (128 rows each)
    const size_t goff = (size_t)bh * NN * DD;
    const int M0 = mt * 128;

    // ---- prologue: async load Q (both) + KV tile 0 ----
    // Q tile: 128 rows x 128 bytes = 1024 x 16B units -> 4 iters of 256 threads
#pragma unroll
    for (int i = 0; i < 4; i++) {
        int u = tid + i * 256;
        int row = u >> 3, cu = u & 7;
        uint32_t sw = sw128(row * 128 + cu * 16);
        const size_t gi = goff + (size_t)(M0 + row) * 64 + cu * 8;
        cpa16(sb + AT_OQH + sw, g_Qh + gi);
        cpa16(sb + AT_OQL + sw, g_Ql + gi);
    }
    attn_load_kv(sb, 0, goff, 0, tid);
    CPA_COMMIT();
    CPA_WAIT(0);
    __syncthreads();

    // ---- Q fragments (resident in registers) ----
    const int a_r = lane & 15;
    const int a_c = (lane >> 4) << 3;
    uint32_t qh[4][4], ql[4][4];
#pragma unroll
    for (int ks = 0; ks < 4; ks++) {
        uint32_t sw = sw128((wid * 16 + a_r) * 128 + (ks * 16 + a_c) * 2);
        ldsm_x4(qh[ks], sb + AT_OQH + sw);
        ldsm_x4(ql[ks], sb + AT_OQL + sw);
    }

    // softmax state (2 row-halves per thread)
    float m0 = -1e30f, m1 = -1e30f, l0 = 0.0f, l1 = 0.0f;
    float o[8][4];
#pragma unroll
    for (int d = 0; d < 8; d++)
#pragma unroll
        for (int v = 0; v < 4; v++) o[d][v] = 0.0f;

    const int b_r = (lane & 7) + ((lane >> 4) << 3);
    const int b_c = ((lane >> 3) & 1) << 3;
    const int v_r = (lane & 7) + (((lane >> 3) & 1) << 3);
    const int v_cu = (lane >> 4) << 4;       // byte offset of 8-elem col group

    for (int c = 0; c < 16; c++) {
        const int s = c & 1;
        if (c > 0) { CPA_WAIT(0); __syncthreads(); }
        if (c + 1 < 16) { attn_load_kv(sb, s ^ 1, goff, (c + 1) * 64, tid); CPA_COMMIT(); }

        const uint32_t kh_b = sb + AT_ST(s) + AT_KH;
        const uint32_t kl_b = sb + AT_ST(s) + AT_KL;
        const uint32_t vh_b = sb + AT_ST(s) + AT_VH;
        const uint32_t vl_b = sb + AT_ST(s) + AT_VL;

        // ---- scores: S = Qh*Kh + Qh*Kl + Ql*Kh ----
        float sc[8][4];
#pragma unroll
        for (int nt = 0; nt < 8; nt++)
#pragma unroll
            for (int v = 0; v < 4; v++) sc[nt][v] = 0.0f;

#pragma unroll
        for (int ks = 0; ks < 4; ks++) {
            uint32_t kh[4][4], kl[4][4];
            const int bo_c = (ks * 16 + b_c) * 2;
#pragma unroll
            for (int g = 0; g < 4; g++) {
                uint32_t sw = sw128((g * 16 + b_r) * 128 + bo_c);
                ldsm_x4(kh[g], kh_b + sw);
                ldsm_x4(kl[g], kl_b + sw);
            }
#pragma unroll
            for (int nt = 0; nt < 8; nt++) {
                const uint32_t* bh_ = &kh[nt >> 1][(nt & 1) * 2];
                const uint32_t* bl_ = &kl[nt >> 1][(nt & 1) * 2];
                mma16816(sc[nt], qh[ks], bh_);
                mma16816(sc[nt], qh[ks], bl_);
                mma16816(sc[nt], ql[ks], bh_);
            }
        }

        // ---- online softmax ----
        float mx0 = sc[0][0], mx1 = sc[0][2];
#pragma unroll
        for (int nt = 0; nt < 8; nt++) {
            mx0 = fmaxf(mx0, fmaxf(sc[nt][0], sc[nt][1]));
            mx1 = fmaxf(mx1, fmaxf(sc[nt][2], sc[nt][3]));
        }
        mx0 = fmaxf(mx0, __shfl_xor_sync(0xffffffffu, mx0, 1));
        mx0 = fmaxf(mx0, __shfl_xor_sync(0xffffffffu, mx0, 2));
        mx1 = fmaxf(mx1, __shfl_xor_sync(0xffffffffu, mx1, 1));
        mx1 = fmaxf(mx1, __shfl_xor_sync(0xffffffffu, mx1, 2));
        const float mn0 = fmaxf(m0, mx0), mn1 = fmaxf(m1, mx1);
        const float al0 = ex2(m0 - mn0), al1 = ex2(m1 - mn1);
        m0 = mn0; m1 = mn1;

        float s0 = 0.0f, s1 = 0.0f;
#pragma unroll
        for (int nt = 0; nt < 8; nt++) {
            sc[nt][0] = ex2(sc[nt][0] - mn0);
            sc[nt][1] = ex2(sc[nt][1] - mn0);
            sc[nt][2] = ex2(sc[nt][2] - mn1);
            sc[nt][3] = ex2(sc[nt][3] - mn1);
            s0 += sc[nt][0] + sc[nt][1];
            s1 += sc[nt][2] + sc[nt][3];
        }
        s0 += __shfl_xor_sync(0xffffffffu, s0, 1);
        s0 += __shfl_xor_sync(0xffffffffu, s0, 2);
        s1 += __shfl_xor_sync(0xffffffffu, s1, 1);
        s1 += __shfl_xor_sync(0xffffffffu, s1, 2);
        l0 = l0 * al0 + s0;
        l1 = l1 * al1 + s1;
#pragma unroll
        for (int d = 0; d < 8; d++) {
            o[d][0] *= al0; o[d][1] *= al0;
            o[d][2] *= al1; o[d][3] *= al1;
        }

        // ---- PV: O += Ph*Vh + Ph*Vl + Pl*Vh ----
#pragma unroll
        for (int jk = 0; jk < 4; jk++) {
            uint32_t ph[4], pl[4];
            {
                float r0, r1, r2, r3, r4, r5, r6, r7;
                ph[0] = packbf_res(sc[2 * jk][0],     sc[2 * jk][1],     r0, r1);
                ph[1] = packbf_res(sc[2 * jk][2],     sc[2 * jk][3],     r2, r3);
                ph[2] = packbf_res(sc[2 * jk + 1][0], sc[2 * jk + 1][1], r4, r5);
                ph[3] = packbf_res(sc[2 * jk + 1][2], sc[2 * jk + 1][3], r6, r7);
                pl[0] = packbf(r0, r1);
                pl[1] = packbf(r2, r3);
                pl[2] = packbf(r4, r5);
                pl[3] = packbf(r6, r7);
            }
            uint32_t vh[4][4], vl[4][4];
            const int vrow = jk * 16 + v_r;
#pragma unroll
            for (int g = 0; g < 4; g++) {
                uint32_t sw = sw128(vrow * 128 + g * 32 + v_cu);
                ldsm_x4_t(vh[g], vh_b + sw);
                ldsm_x4_t(vl[g], vl_b + sw);
            }
#pragma unroll
            for (int dt = 0; dt < 8; dt++) {
                const uint32_t* bvh = &vh[dt >> 1][(dt & 1) * 2];
                const uint32_t* bvl = &vl[dt >> 1][(dt & 1) * 2];
                mma16816(o[dt], ph, bvh);
                mma16816(o[dt], ph, bvl);
                mma16816(o[dt], pl, bvh);
            }
        }
        __syncthreads();
    }

    // ---- epilogue: normalize, write bf16x3 ctx rows into g_C3 ----
    const int b = bh >> 4;
    const int h = bh & 15;
    const float inv0 = 1.0f / l0, inv1 = 1.0f / l1;
    const int tok0 = M0 + wid * 16 + (lane >> 2);
    __nv_bfloat16* row0 = g_C3 + (size_t)(b * NN + tok0) * KP;
    __nv_bfloat16* row1 = row0 + (size_t)8 * KP;
#pragma unroll
    for (int dt = 0; dt < 8; dt++) {
        const int k = h * 64 + dt * 8 + ((lane & 3) << 1);
        float r0, r1;
        uint32_t hi0 = packbf_res(o[dt][0] * inv0, o[dt][1] * inv0, r0, r1);
        uint32_t lo0 = packbf(r0, r1);
        *(uint32_t*)(row0 + k) = hi0;
        *(uint32_t*)(row0 + 1024 + k) = hi0;
        *(uint32_t*)(row0 + 2048 + k) = lo0;
        uint32_t hi1 = packbf_res(o[dt][2] * inv1, o[dt][3] * inv1, r0, r1);
        uint32_t lo1 = packbf(r0, r1);
        *(uint32_t*)(row1 + k) = hi1;
        *(uint32_t*)(row1 + 1024 + k) = hi1;
        *(uint32_t*)(row1 + 2048 + k) = lo1;
    }
}

// ---------------------------------------------------------------------------
// Preprocessing splits
// ---------------------------------------------------------------------------
__global__ void split_act(const float* __restrict__ src)
{
    const int i = blockIdx.x * 256 + threadIdx.x;
    const int m = i >> 8;
    const int k = (i & 255) << 2;
    float4 v = ((const float4*)src)[i];

    __nv_bfloat16 h0 = __float2bfloat16(v.x), h1 = __float2bfloat16(v.y);
    __nv_bfloat16 h2 = __float2bfloat16(v.z), h3 = __float2bfloat16(v.w);
    __nv_bfloat16 l0 = __float2bfloat16(v.x - __bfloat162float(h0));
    __nv_bfloat16 l1 = __float2bfloat16(v.y - __bfloat162float(h1));
    __nv_bfloat16 l2 = __float2bfloat16(v.z - __bfloat162float(h2));
    __nv_bfloat16 l3 = __float2bfloat16(v.w - __bfloat162float(h3));

    __nv_bfloat162 hA, hB, lA, lB;
    hA.x = h0; hA.y = h1; hB.x = h2; hB.y = h3;
    lA.x = l0; lA.y = l1; lB.x = l2; lB.y = l3;

    __nv_bfloat16* row = g_A3 + (size_t)m * KP;
    *(__nv_bfloat162*)(row + k)        = hA;
    *(__nv_bfloat162*)(row + k + 2)    = hB;
    *(__nv_bfloat162*)(row + 1024 + k) = hA;
    *(__nv_bfloat162*)(row + 1026 + k) = hB;
    *(__nv_bfloat162*)(row + 2048 + k) = lA;
    *(__nv_bfloat162*)(row + 2050 + k) = lB;
}

template <int W>
__global__ void split_w(const float* __restrict__ w)
{
    __nv_bfloat16* dst = (W == 0) ? g_W3 : g_P3;
    const int Nw = (W == 0) ? 3072 : 1024;
    __shared__ float t[32][33];
    const int n0 = blockIdx.x * 32, k0 = blockIdx.y * 32;
    const int tx = threadIdx.x, ty = threadIdx.y;

#pragma unroll
    for (int i = 0; i < 32; i += 8)
        t[ty + i][tx] = w[(size_t)(k0 + ty + i) * Nw + n0 + tx];
    __syncthreads();
#pragma unroll
    for (int i = 0; i < 32; i += 8) {
        const int n = n0 + ty + i, k = k0 + tx;
        const float x = t[tx][ty + i];
        const __nv_bfloat16 h = __float2bfloat16(x);
        const __nv_bfloat16 l = __float2bfloat16(x - __bfloat162float(h));
        __nv_bfloat16* row = dst + (size_t)n * KP;
        row[k] = h;
        row[1024 + k] = l;
        row[2048 + k] = h;
    }
}

// ---------------------------------------------------------------------------
extern "C" void kernel_launch(void* const* d_in, const int* in_sizes, int n_in,
                              void* d_out, int out_size)
{
    const float* hidden = (const float*)d_in[0];
    const float* qkv_w  = (const float*)d_in[1];
    const float* qkv_b  = (const float*)d_in[2];
    const float* proj_w = (const float*)d_in[3];
    const float* proj_b = (const float*)d_in[4];
    float* out = (float*)d_out;

    cudaFuncSetAttribute(hmma_gemm<0>, cudaFuncAttributeMaxDynamicSharedMemorySize, GEMM_SMEM);
    cudaFuncSetAttribute(hmma_gemm<1>, cudaFuncAttributeMaxDynamicSharedMemorySize, GEMM_SMEM);
    cudaFuncSetAttribute(attn_hmma, cudaFuncAttributeMaxDynamicSharedMemorySize, ATTN_SMEM);

    // 1) splits
    split_act<<<16384, 256>>>(hidden);
    {
        dim3 g0(3072 / 32, 1024 / 32);
        split_w<0><<<g0, dim3(32, 8)>>>(qkv_w);
        dim3 g1(1024 / 32, 1024 / 32);
        split_w<1><<<g1, dim3(32, 8)>>>(proj_w);
    }

    // 2) QKV GEMM -> Q/K/V bf16 hi/lo
    {
        dim3 grid(3072 / 128, MTOT / 128);
        hmma_gemm<0><<<grid, 256, GEMM_SMEM>>>(qkv_b, nullptr);
    }

    // 3) Flash attention (HMMA) -> g_C3
    {
        dim3 grid(BB * HH, NN / 128);   // (256, 8)
        attn_hmma<<<grid, 256, ATTN_SMEM>>>();
    }

    // 4) projection GEMM -> out
    {
        dim3 grid(1024 / 128, MTOT / 128);
        hmma_gemm<1><<<grid, 256, GEMM_SMEM>>>(proj_b, out);
    }
}